// round 2
// baseline (speedup 1.0000x reference)
#include <cuda_runtime.h>
#include <cuda_fp16.h>
#include <math.h>

#define TT   5        // edge types
#define CC   2        // channels
#define NN   4096     // nodes
#define EE   150000   // edges per type
#define WIN  512
#define WOUT 128
#define NT   1024     // targets
#define NCLS 16

// ---------------- scratch (static device memory only) ----------------
__device__ int   g_cnt[TT * NN];
__device__ int   g_rowptr[TT * (NN + 1)];
__device__ int   g_cursor[TT * NN];
__device__ int   g_dst[TT * EE];
__device__ float g_valv[TT * EE];
__device__ float g_f1[CC * TT], g_f2[CC * TT], g_f3[CC * TT];
// fp16 payloads for the gather stages (fp32 accumulation everywhere)
__device__ __align__(16) __half g_XWh[NN * WOUT];          // [node][128]
__device__ __align__(16) __half g_Y3h[NN * 2 * WOUT];      // [node][lane][ch0 x4, ch1 x4]
__device__ __align__(16) __half g_Y2h[NN * 2 * WOUT];      // same interleaved layout
__device__ float g_rs[TT * NN];
__device__ float g_s2[CC * NN];
__device__ float g_t3[CC * NN];
__device__ float g_u [CC * NN];
__device__ __align__(16) float g_Xt[NT * CC * WOUT];

// ---------------- helpers ----------------
struct H8 { __half2 a, b, c, d; };   // 16 bytes = 8 halfs

// ---------------- kernels ----------------

__global__ void zero_k() {
    int i = blockIdx.x * blockDim.x + threadIdx.x;
    if (i < TT * NN) g_cnt[i] = 0;
}

__global__ void softmax_k(const float* w1, const float* w2, const float* w3) {
    int tid = threadIdx.x;
    if (tid < 6) {
        int m = tid >> 1, c = tid & 1;
        const float* w = (m == 0 ? w1 : (m == 1 ? w2 : w3)) + c * TT;
        float*       f = (m == 0 ? g_f1 : (m == 1 ? g_f2 : g_f3)) + c * TT;
        float mx = w[0];
        for (int j = 1; j < TT; j++) mx = fmaxf(mx, w[j]);
        float e[TT], s = 0.f;
        for (int j = 0; j < TT; j++) { e[j] = expf(w[j] - mx); s += e[j]; }
        float inv = 1.f / s;
        for (int j = 0; j < TT; j++) f[j] = e[j] * inv;
    }
}

__global__ void count_k(const int* __restrict__ edge_index) {
    int gid = blockIdx.x * blockDim.x + threadIdx.x;
    if (gid >= TT * EE) return;
    int j = gid / EE, e = gid - j * EE;
    int src = edge_index[j * 2 * EE + e];
    atomicAdd(&g_cnt[j * NN + src], 1);
}

// exclusive scan per type: 256 threads x 16 rows, register-resident
__global__ void __launch_bounds__(256) scan_k() {
    int j = blockIdx.x, tid = threadIdx.x;
    const int R = 16;
    int base = j * NN + tid * R;
    int v[R];
    int s = 0;
#pragma unroll
    for (int i = 0; i < R; i++) { v[i] = g_cnt[base + i]; s += v[i]; }
    __shared__ int warpsum[8];
    int lane = tid & 31, w = tid >> 5;
    int pre = s;
#pragma unroll
    for (int off = 1; off < 32; off <<= 1) {
        int t = __shfl_up_sync(~0u, pre, off);
        if (lane >= off) pre += t;
    }
    if (lane == 31) warpsum[w] = pre;
    __syncthreads();
    if (w == 0) {
        int ws = (lane < 8) ? warpsum[lane] : 0;
#pragma unroll
        for (int off = 1; off < 8; off <<= 1) {
            int t = __shfl_up_sync(~0u, ws, off);
            if (lane >= off) ws += t;
        }
        if (lane < 8) warpsum[lane] = ws;
    }
    __syncthreads();
    int run = pre - s + (w > 0 ? warpsum[w - 1] : 0);
#pragma unroll
    for (int i = 0; i < R; i++) {
        g_rowptr[j * (NN + 1) + tid * R + i] = run;
        g_cursor[base + i] = run;
        run += v[i];
    }
    if (tid == 255) g_rowptr[j * (NN + 1) + NN] = run;
}

__global__ void scatter_k(const int* __restrict__ edge_index,
                          const float* __restrict__ edge_value) {
    int gid = blockIdx.x * blockDim.x + threadIdx.x;
    if (gid >= TT * EE) return;
    int j = gid / EE, e = gid - j * EE;
    int src = edge_index[j * 2 * EE + e];
    int dst = edge_index[j * 2 * EE + EE + e];
    float v = edge_value[j * EE + e];
    int pos = atomicAdd(&g_cursor[j * NN + src], 1);
    g_dst [j * EE + pos] = dst;
    g_valv[j * EE + pos] = v;
}

// XW = X @ gcn_w : [4096,512] @ [512,128] -> fp16 output
__global__ void __launch_bounds__(256) gemm_k(const float* __restrict__ X,
                                              const float* __restrict__ Wt) {
    __shared__ float Xs[32][33];
    __shared__ float Ws[32][WOUT];
    int tid = threadIdx.x;
    int cx = tid & 31;
    int cy = tid >> 5;
    int row0 = blockIdx.x * 32;
    float acc[4][4];
#pragma unroll
    for (int i = 0; i < 4; i++)
#pragma unroll
        for (int k = 0; k < 4; k++) acc[i][k] = 0.f;

    for (int k0 = 0; k0 < WIN; k0 += 32) {
#pragma unroll
        for (int i = 0; i < 4; i++) {
            int li = tid + i * 256;
            int r = li >> 5, c = li & 31;
            Xs[r][c] = X[(row0 + r) * WIN + k0 + c];
        }
#pragma unroll
        for (int i = 0; i < 4; i++) {
            int li = tid + i * 256;
            int r = li >> 5, c4 = li & 31;
            *(float4*)&Ws[r][c4 * 4] = *(const float4*)&Wt[(k0 + r) * WOUT + c4 * 4];
        }
        __syncthreads();
#pragma unroll
        for (int kk = 0; kk < 32; kk++) {
            float xv[4];
#pragma unroll
            for (int i = 0; i < 4; i++) xv[i] = Xs[cy * 4 + i][kk];
            float4 wv = *(float4*)&Ws[kk][cx * 4];
#pragma unroll
            for (int i = 0; i < 4; i++) {
                acc[i][0] += xv[i] * wv.x;
                acc[i][1] += xv[i] * wv.y;
                acc[i][2] += xv[i] * wv.z;
                acc[i][3] += xv[i] * wv.w;
            }
        }
        __syncthreads();
    }
#pragma unroll
    for (int i = 0; i < 4; i++) {
        __half2 h0 = __floats2half2_rn(acc[i][0], acc[i][1]);
        __half2 h1 = __floats2half2_rn(acc[i][2], acc[i][3]);
        __half2* p = (__half2*)&g_XWh[(row0 + cy * 4 + i) * WOUT + cx * 4];
        p[0] = h0; p[1] = h1;
    }
}

__global__ void rs_k() {
    int gid = blockIdx.x * blockDim.x + threadIdx.x;
    if (gid >= TT * NN) return;
    int j = gid / NN, r = gid - j * NN;
    int s = g_rowptr[j * (NN + 1) + r], e = g_rowptr[j * (NN + 1) + r + 1];
    const float* vp = g_valv + j * EE;
    float acc = 0.f;
    for (int k = s; k < e; k++) acc += vp[k];
    g_rs[gid] = acc;
}

__global__ void s2t3_k() {
    int gid = blockIdx.x * blockDim.x + threadIdx.x;
    if (gid >= CC * NN) return;
    int c = gid >> 12, r = gid & (NN - 1);
    float s2 = 0.f, t3 = 0.f;
#pragma unroll
    for (int j = 0; j < TT; j++) {
        float rs = g_rs[j * NN + r];
        s2 += g_f2[c * TT + j] * rs;
        t3 += g_f3[c * TT + j] * rs;
    }
    g_s2[gid] = s2;
    g_t3[gid] = t3;
}

__global__ void u_k() {
    int gid = blockIdx.x * blockDim.x + threadIdx.x;
    if (gid >= CC * NN) return;
    int c = gid >> 12, r = gid & (NN - 1);
    float acc = 0.f;
#pragma unroll
    for (int j = 0; j < TT; j++) {
        float f = g_f2[c * TT + j];
        int s = g_rowptr[j * (NN + 1) + r], e = g_rowptr[j * (NN + 1) + r + 1];
        const int* dp = g_dst + j * EE;
        const float* vp = g_valv + j * EE;
        for (int k = s; k < e; k++)
            acc += f * vp[k] * g_t3[c * NN + dp[k]];
    }
    g_u[gid] = acc;
}

// Stage A: Y3[c] = Q3_c @ XW ; gather fp16 XW (8B/lane/edge), write interleaved fp16
__global__ void __launch_bounds__(256) stageA_k() {
    int wid = (blockIdx.x << 3) + (threadIdx.x >> 5);
    if (wid >= NN) return;
    int lane = threadIdx.x & 31;
    float4 a0 = make_float4(0, 0, 0, 0), a1 = make_float4(0, 0, 0, 0);
#pragma unroll
    for (int j = 0; j < TT; j++) {
        float c0 = g_f3[0 * TT + j], c1 = g_f3[1 * TT + j];
        int s = g_rowptr[j * (NN + 1) + wid], e = g_rowptr[j * (NN + 1) + wid + 1];
        const int* dp = g_dst + j * EE;
        const float* vp = g_valv + j * EE;
#pragma unroll 4
        for (int k = s; k < e; k++) {
            int d = dp[k];
            float v = vp[k];
            const __half2* xp = (const __half2*)&g_XWh[d * WOUT + lane * 4];
            float2 x01 = __half22float2(xp[0]);
            float2 x23 = __half22float2(xp[1]);
            float w0 = c0 * v, w1 = c1 * v;
            a0.x += w0 * x01.x; a0.y += w0 * x01.y; a0.z += w0 * x23.x; a0.w += w0 * x23.y;
            a1.x += w1 * x01.x; a1.y += w1 * x01.y; a1.z += w1 * x23.x; a1.w += w1 * x23.y;
        }
    }
    H8 o;
    o.a = __floats2half2_rn(a0.x, a0.y);
    o.b = __floats2half2_rn(a0.z, a0.w);
    o.c = __floats2half2_rn(a1.x, a1.y);
    o.d = __floats2half2_rn(a1.z, a1.w);
    *(H8*)&g_Y3h[wid * 256 + lane * 8] = o;
}

// Stage B: Y2[c] = Q2_c @ Y3[c] ; single 16B gather per edge per lane (both channels)
__global__ void __launch_bounds__(256) stageB_k() {
    int wid = (blockIdx.x << 3) + (threadIdx.x >> 5);
    if (wid >= NN) return;
    int lane = threadIdx.x & 31;
    float4 a0 = make_float4(0, 0, 0, 0), a1 = make_float4(0, 0, 0, 0);
#pragma unroll
    for (int j = 0; j < TT; j++) {
        float c0 = g_f2[0 * TT + j], c1 = g_f2[1 * TT + j];
        int s = g_rowptr[j * (NN + 1) + wid], e = g_rowptr[j * (NN + 1) + wid + 1];
        const int* dp = g_dst + j * EE;
        const float* vp = g_valv + j * EE;
#pragma unroll 4
        for (int k = s; k < e; k++) {
            int d = dp[k];
            float v = vp[k];
            H8 y = *(const H8*)&g_Y3h[d * 256 + lane * 8];
            float2 y00 = __half22float2(y.a);
            float2 y01 = __half22float2(y.b);
            float2 y10 = __half22float2(y.c);
            float2 y11 = __half22float2(y.d);
            float w0 = c0 * v, w1 = c1 * v;
            a0.x += w0 * y00.x; a0.y += w0 * y00.y; a0.z += w0 * y01.x; a0.w += w0 * y01.y;
            a1.x += w1 * y10.x; a1.y += w1 * y10.y; a1.z += w1 * y11.x; a1.w += w1 * y11.y;
        }
    }
    H8 o;
    o.a = __floats2half2_rn(a0.x, a0.y);
    o.b = __floats2half2_rn(a0.z, a0.w);
    o.c = __floats2half2_rn(a1.x, a1.y);
    o.d = __floats2half2_rn(a1.z, a1.w);
    *(H8*)&g_Y2h[wid * 256 + lane * 8] = o;
}

// Stage C: target rows only
__global__ void __launch_bounds__(256) stageC_k(const int* __restrict__ target,
                                                const float* __restrict__ gcn_b) {
    int w = (blockIdx.x << 3) + (threadIdx.x >> 5);
    if (w >= NT * CC) return;
    int t = w >> 1, c = w & 1;
    int lane = threadIdx.x & 31;
    int row = target[t];
    float4 acc = make_float4(0, 0, 0, 0);
    float d1 = 0.f, d2 = 0.f;
#pragma unroll
    for (int j = 0; j < TT; j++) {
        float cf = g_f1[c * TT + j];
        int s = g_rowptr[j * (NN + 1) + row], e = g_rowptr[j * (NN + 1) + row + 1];
        const int* dp = g_dst + j * EE;
        const float* vp = g_valv + j * EE;
#pragma unroll 4
        for (int k = s; k < e; k++) {
            int d = dp[k];
            float v = vp[k];
            float wv = cf * v;
            const __half2* yp = (const __half2*)&g_Y2h[d * 256 + lane * 8 + c * 4];
            float2 y01 = __half22float2(yp[0]);
            float2 y23 = __half22float2(yp[1]);
            acc.x += wv * y01.x; acc.y += wv * y01.y; acc.z += wv * y23.x; acc.w += wv * y23.y;
            d1 += wv * g_s2[c * NN + d];
            d2 += wv * g_u [c * NN + d];
        }
    }
    float inv1 = (d1 == 0.f) ? 0.f : 1.f / d1;
    float deg2 = inv1 * d2;
    float inv2 = (deg2 == 0.f) ? 0.f : 1.f / deg2;
    float sc = inv1 * inv2;
    int colb = lane * 4;
    float4 b = *(const float4*)&gcn_b[colb];
    float4 o;
    o.x = fmaxf(sc * acc.x + b.x, 0.f);
    o.y = fmaxf(sc * acc.y + b.y, 0.f);
    o.z = fmaxf(sc * acc.z + b.z, 0.f);
    o.w = fmaxf(sc * acc.w + b.w, 0.f);
    *(float4*)&g_Xt[t * (CC * WOUT) + c * WOUT + colb] = o;
}

// y = Xt @ lin_w + lin_b : [1024,256] @ [256,16]
__global__ void final_k(const float* __restrict__ lin_w,
                        const float* __restrict__ lin_b,
                        float* __restrict__ out) {
    int gid = blockIdx.x * blockDim.x + threadIdx.x;
    if (gid >= NT * NCLS) return;
    int t = gid >> 4, cls = gid & 15;
    float acc = lin_b[cls];
    const float* xr = g_Xt + t * (CC * WOUT);
#pragma unroll 8
    for (int k = 0; k < CC * WOUT; k++)
        acc += xr[k] * lin_w[k * NCLS + cls];
    out[gid] = acc;
}

// ---------------- launch ----------------
extern "C" void kernel_launch(void* const* d_in, const int* in_sizes, int n_in,
                              void* d_out, int out_size) {
    const int*   edge_index = (const int*)d_in[0];
    const float* edge_value = (const float*)d_in[1];
    const float* X          = (const float*)d_in[2];
    const int*   target_x   = (const int*)d_in[3];
    const float* w_l0_c1    = (const float*)d_in[4];
    const float* w_l0_c2    = (const float*)d_in[5];
    const float* w_l1_c1    = (const float*)d_in[6];
    const float* gcn_w      = (const float*)d_in[7];
    const float* gcn_b      = (const float*)d_in[8];
    const float* lin_w      = (const float*)d_in[9];
    const float* lin_b      = (const float*)d_in[10];
    float* out = (float*)d_out;

    zero_k<<<(TT * NN + 255) / 256, 256>>>();
    softmax_k<<<1, 32>>>(w_l0_c1, w_l0_c2, w_l1_c1);
    count_k<<<(TT * EE + 255) / 256, 256>>>(edge_index);
    scan_k<<<TT, 256>>>();
    scatter_k<<<(TT * EE + 255) / 256, 256>>>(edge_index, edge_value);
    gemm_k<<<NN / 32, 256>>>(X, gcn_w);
    rs_k<<<(TT * NN + 255) / 256, 256>>>();
    s2t3_k<<<(CC * NN + 255) / 256, 256>>>();
    u_k<<<(CC * NN + 255) / 256, 256>>>();
    stageA_k<<<NN / 8, 256>>>();
    stageB_k<<<NN / 8, 256>>>();
    stageC_k<<<(NT * CC) / 8, 256>>>(target_x, gcn_b);
    final_k<<<(NT * NCLS + 255) / 256, 256>>>(lin_w, lin_b, out);
}

// round 3
// speedup vs baseline: 1.5064x; 1.5064x over previous
#include <cuda_runtime.h>
#include <cuda_fp16.h>
#include <math.h>

#define TT   5
#define CC   2
#define NN   4096
#define EE   150000
#define WIN  512
#define WOUT 128
#define NT   1024
#define NCLS 16

// ---------------- static scratch ----------------
__device__ int   g_cnt[TT * NN];
__device__ int   g_rowptr[TT * (NN + 1)];
__device__ int   g_cursor[TT * NN];
__device__ int   g_dst[TT * EE];
__device__ float g_valv[TT * EE];
__device__ float g_f1[CC * TT], g_f2[CC * TT], g_f3[CC * TT];
__device__ float g_rs[TT * NN];
__device__ __align__(16) float4 g_s2t3[NN];   // {s2_c0, s2_c1, t3_c0, t3_c1}
__device__ __align__(8)  float2 g_u2[NN];     // {u_c0, u_c1}
__device__ __align__(16) __half g_XWh[NN * WOUT];       // [node][128]
__device__ __align__(16) __half g_Y3h[NN * 2 * WOUT];   // [node][lane][ch0 x4, ch1 x4]
__device__ __align__(16) __half g_Y2h[NN * 2 * WOUT];

struct __align__(16) H8 { __half2 a, b, c, d; };

// ---------------- launch 1: gemm + zero counters + softmax ----------------
// blocks [0,128): gemm XW=X@gcn_w -> fp16 ; blocks [128,208): zero cnt/rs ; block 208: softmax
__global__ void __launch_bounds__(256) prep_k(const float* __restrict__ X,
                                              const float* __restrict__ Wt,
                                              const float* __restrict__ w1,
                                              const float* __restrict__ w2,
                                              const float* __restrict__ w3) {
    int b = blockIdx.x;
    if (b < 128) {
        __shared__ float Xs[32][33];
        __shared__ float Ws[32][WOUT];
        int tid = threadIdx.x;
        int cx = tid & 31;
        int cy = tid >> 5;
        int row0 = b * 32;
        float acc[4][4];
#pragma unroll
        for (int i = 0; i < 4; i++)
#pragma unroll
            for (int k = 0; k < 4; k++) acc[i][k] = 0.f;
        for (int k0 = 0; k0 < WIN; k0 += 32) {
#pragma unroll
            for (int i = 0; i < 4; i++) {
                int li = tid + i * 256;
                int r = li >> 5, c = li & 31;
                Xs[r][c] = X[(row0 + r) * WIN + k0 + c];
            }
#pragma unroll
            for (int i = 0; i < 4; i++) {
                int li = tid + i * 256;
                int r = li >> 5, c4 = li & 31;
                *(float4*)&Ws[r][c4 * 4] = *(const float4*)&Wt[(k0 + r) * WOUT + c4 * 4];
            }
            __syncthreads();
#pragma unroll
            for (int kk = 0; kk < 32; kk++) {
                float xv[4];
#pragma unroll
                for (int i = 0; i < 4; i++) xv[i] = Xs[cy * 4 + i][kk];
                float4 wv = *(float4*)&Ws[kk][cx * 4];
#pragma unroll
                for (int i = 0; i < 4; i++) {
                    acc[i][0] += xv[i] * wv.x;
                    acc[i][1] += xv[i] * wv.y;
                    acc[i][2] += xv[i] * wv.z;
                    acc[i][3] += xv[i] * wv.w;
                }
            }
            __syncthreads();
        }
#pragma unroll
        for (int i = 0; i < 4; i++) {
            __half2 h0 = __floats2half2_rn(acc[i][0], acc[i][1]);
            __half2 h1 = __floats2half2_rn(acc[i][2], acc[i][3]);
            __half2* p = (__half2*)&g_XWh[(row0 + cy * 4 + i) * WOUT + cx * 4];
            p[0] = h0; p[1] = h1;
        }
    } else if (b < 208) {
        int i = (b - 128) * 256 + threadIdx.x;
        if (i < TT * NN) { g_cnt[i] = 0; g_rs[i] = 0.f; }
    } else {
        int tid = threadIdx.x;
        if (tid < 6) {
            int m = tid >> 1, c = tid & 1;
            const float* w = (m == 0 ? w1 : (m == 1 ? w2 : w3)) + c * TT;
            float*       f = (m == 0 ? g_f1 : (m == 1 ? g_f2 : g_f3)) + c * TT;
            float mx = w[0];
            for (int j = 1; j < TT; j++) mx = fmaxf(mx, w[j]);
            float e[TT], s = 0.f;
            for (int j = 0; j < TT; j++) { e[j] = expf(w[j] - mx); s += e[j]; }
            float inv = 1.f / s;
            for (int j = 0; j < TT; j++) f[j] = e[j] * inv;
        }
    }
}

// ---------------- launch 2: count + per-type row sums ----------------
__global__ void count_k(const int* __restrict__ edge_index,
                        const float* __restrict__ edge_value) {
    int gid = blockIdx.x * blockDim.x + threadIdx.x;
    if (gid >= TT * EE) return;
    int j = gid / EE, e = gid - j * EE;
    int src = edge_index[j * 2 * EE + e];
    atomicAdd(&g_cnt[j * NN + src], 1);
    atomicAdd(&g_rs[j * NN + src], edge_value[j * EE + e]);
}

// ---------------- launch 3: scan (blocks 0-4) + s2/t3 (blocks 5-20) ----------------
__global__ void __launch_bounds__(256) scan_s2t3_k() {
    int b = blockIdx.x, tid = threadIdx.x;
    if (b < TT) {
        const int R = 16;
        int j = b;
        int base = j * NN + tid * R;
        int v[R];
        int s = 0;
#pragma unroll
        for (int i = 0; i < R; i++) { v[i] = g_cnt[base + i]; s += v[i]; }
        __shared__ int warpsum[8];
        int lane = tid & 31, w = tid >> 5;
        int pre = s;
#pragma unroll
        for (int off = 1; off < 32; off <<= 1) {
            int t = __shfl_up_sync(~0u, pre, off);
            if (lane >= off) pre += t;
        }
        if (lane == 31) warpsum[w] = pre;
        __syncthreads();
        if (w == 0) {
            int ws = (lane < 8) ? warpsum[lane] : 0;
#pragma unroll
            for (int off = 1; off < 8; off <<= 1) {
                int t = __shfl_up_sync(~0u, ws, off);
                if (lane >= off) ws += t;
            }
            if (lane < 8) warpsum[lane] = ws;
        }
        __syncthreads();
        int run = pre - s + (w > 0 ? warpsum[w - 1] : 0);
#pragma unroll
        for (int i = 0; i < R; i++) {
            g_rowptr[j * (NN + 1) + tid * R + i] = run;
            g_cursor[base + i] = run;
            run += v[i];
        }
        if (tid == 255) g_rowptr[j * (NN + 1) + NN] = run;
    } else {
        int r = (b - TT) * 256 + tid;
        if (r < NN) {
            float s20 = 0.f, s21 = 0.f, t30 = 0.f, t31 = 0.f;
#pragma unroll
            for (int j = 0; j < TT; j++) {
                float rs = g_rs[j * NN + r];
                s20 += g_f2[j] * rs;       s21 += g_f2[TT + j] * rs;
                t30 += g_f3[j] * rs;       t31 += g_f3[TT + j] * rs;
            }
            g_s2t3[r] = make_float4(s20, s21, t30, t31);
        }
    }
}

// ---------------- launch 4: scatter into CSR ----------------
__global__ void scatter_k(const int* __restrict__ edge_index,
                          const float* __restrict__ edge_value) {
    int gid = blockIdx.x * blockDim.x + threadIdx.x;
    if (gid >= TT * EE) return;
    int j = gid / EE, e = gid - j * EE;
    int src = edge_index[j * 2 * EE + e];
    int dst = edge_index[j * 2 * EE + EE + e];
    float v = edge_value[j * EE + e];
    int pos = atomicAdd(&g_cursor[j * NN + src], 1);
    g_dst [j * EE + pos] = dst;
    g_valv[j * EE + pos] = v;
}

// ---------------- launch 5: stageA (blocks 0-2047, 4 warps/row) + u (blocks 2048-2559) ----------------
__global__ void __launch_bounds__(256) stageAu_k() {
    int b = blockIdx.x;
    int tid = threadIdx.x, w = tid >> 5, lane = tid & 31;
    if (b < 2048) {
        __shared__ float sm[8][8][33];
        int row = b * 2 + (w >> 2);
        int q = w & 3;
        float4 a0 = make_float4(0, 0, 0, 0), a1 = make_float4(0, 0, 0, 0);
#pragma unroll
        for (int j = 0; j < TT; j++) {
            float c0 = g_f3[j], c1 = g_f3[TT + j];
            int s = g_rowptr[j * (NN + 1) + row], e = g_rowptr[j * (NN + 1) + row + 1];
            int len = e - s;
            int qs = s + ((len * q) >> 2), qe = s + ((len * (q + 1)) >> 2);
            const int* dp = g_dst + j * EE;
            const float* vp = g_valv + j * EE;
#pragma unroll 4
            for (int k = qs; k < qe; k++) {
                int d = dp[k];
                float v = vp[k];
                int2 raw = *(const int2*)&g_XWh[d * WOUT + lane * 4];
                __half2 h01 = *(__half2*)&raw.x;
                __half2 h23 = *(__half2*)&raw.y;
                float2 x01 = __half22float2(h01);
                float2 x23 = __half22float2(h23);
                float w0 = c0 * v, w1 = c1 * v;
                a0.x += w0 * x01.x; a0.y += w0 * x01.y; a0.z += w0 * x23.x; a0.w += w0 * x23.y;
                a1.x += w1 * x01.x; a1.y += w1 * x01.y; a1.z += w1 * x23.x; a1.w += w1 * x23.y;
            }
        }
        sm[w][0][lane] = a0.x; sm[w][1][lane] = a0.y; sm[w][2][lane] = a0.z; sm[w][3][lane] = a0.w;
        sm[w][4][lane] = a1.x; sm[w][5][lane] = a1.y; sm[w][6][lane] = a1.z; sm[w][7][lane] = a1.w;
        __syncthreads();
        if (q == 0) {
            float vals[8];
#pragma unroll
            for (int i = 0; i < 8; i++)
                vals[i] = sm[w][i][lane] + sm[w + 1][i][lane] + sm[w + 2][i][lane] + sm[w + 3][i][lane];
            H8 o;
            o.a = __floats2half2_rn(vals[0], vals[1]);
            o.b = __floats2half2_rn(vals[2], vals[3]);
            o.c = __floats2half2_rn(vals[4], vals[5]);
            o.d = __floats2half2_rn(vals[6], vals[7]);
            *(H8*)&g_Y3h[row * 256 + lane * 8] = o;
        }
    } else {
        // u[c][r] = sum_j f2[c][j] * sum_k v * t3[c][dst]; warp per row, both channels
        int r = (b - 2048) * 8 + w;
        float acc0 = 0.f, acc1 = 0.f;
#pragma unroll
        for (int j = 0; j < TT; j++) {
            float f0 = g_f2[j], f1 = g_f2[TT + j];
            int s = g_rowptr[j * (NN + 1) + r], e = g_rowptr[j * (NN + 1) + r + 1];
            const int* dp = g_dst + j * EE;
            const float* vp = g_valv + j * EE;
            for (int k = s + lane; k < e; k += 32) {
                int d = dp[k];
                float v = vp[k];
                float4 st = g_s2t3[d];
                acc0 += f0 * v * st.z;
                acc1 += f1 * v * st.w;
            }
        }
#pragma unroll
        for (int off = 16; off > 0; off >>= 1) {
            acc0 += __shfl_down_sync(~0u, acc0, off);
            acc1 += __shfl_down_sync(~0u, acc1, off);
        }
        if (lane == 0) g_u2[r] = make_float2(acc0, acc1);
    }
}

// ---------------- launch 6: stageB, 4 warps/row ----------------
__global__ void __launch_bounds__(256) stageB_k() {
    __shared__ float sm[8][8][33];
    int b = blockIdx.x;
    int tid = threadIdx.x, w = tid >> 5, lane = tid & 31;
    int row = b * 2 + (w >> 2);
    int q = w & 3;
    float4 a0 = make_float4(0, 0, 0, 0), a1 = make_float4(0, 0, 0, 0);
#pragma unroll
    for (int j = 0; j < TT; j++) {
        float c0 = g_f2[j], c1 = g_f2[TT + j];
        int s = g_rowptr[j * (NN + 1) + row], e = g_rowptr[j * (NN + 1) + row + 1];
        int len = e - s;
        int qs = s + ((len * q) >> 2), qe = s + ((len * (q + 1)) >> 2);
        const int* dp = g_dst + j * EE;
        const float* vp = g_valv + j * EE;
#pragma unroll 4
        for (int k = qs; k < qe; k++) {
            int d = dp[k];
            float v = vp[k];
            H8 y = *(const H8*)&g_Y3h[d * 256 + lane * 8];
            float2 y00 = __half22float2(y.a);
            float2 y01 = __half22float2(y.b);
            float2 y10 = __half22float2(y.c);
            float2 y11 = __half22float2(y.d);
            float w0 = c0 * v, w1 = c1 * v;
            a0.x += w0 * y00.x; a0.y += w0 * y00.y; a0.z += w0 * y01.x; a0.w += w0 * y01.y;
            a1.x += w1 * y10.x; a1.y += w1 * y10.y; a1.z += w1 * y11.x; a1.w += w1 * y11.y;
        }
    }
    sm[w][0][lane] = a0.x; sm[w][1][lane] = a0.y; sm[w][2][lane] = a0.z; sm[w][3][lane] = a0.w;
    sm[w][4][lane] = a1.x; sm[w][5][lane] = a1.y; sm[w][6][lane] = a1.z; sm[w][7][lane] = a1.w;
    __syncthreads();
    if (q == 0) {
        float vals[8];
#pragma unroll
        for (int i = 0; i < 8; i++)
            vals[i] = sm[w][i][lane] + sm[w + 1][i][lane] + sm[w + 2][i][lane] + sm[w + 3][i][lane];
        H8 o;
        o.a = __floats2half2_rn(vals[0], vals[1]);
        o.b = __floats2half2_rn(vals[2], vals[3]);
        o.c = __floats2half2_rn(vals[4], vals[5]);
        o.d = __floats2half2_rn(vals[6], vals[7]);
        *(H8*)&g_Y2h[row * 256 + lane * 8] = o;
    }
}

// ---------------- launch 7: stageC + final linear fused. 2 targets/block, 4 warps/target ----------------
__global__ void __launch_bounds__(256) stageC_k(const int* __restrict__ target,
                                                const float* __restrict__ gcn_b,
                                                const float* __restrict__ lin_w,
                                                const float* __restrict__ lin_b,
                                                float* __restrict__ out) {
    __shared__ float sm[8][8][33];
    __shared__ float smd[8][4];
    __shared__ float xts[2][CC * WOUT];
    int b = blockIdx.x;
    int tid = threadIdx.x, w = tid >> 5, lane = tid & 31;
    int tloc = w >> 2, q = w & 3;
    int t = b * 2 + tloc;
    int row = target[t];
    float4 a0 = make_float4(0, 0, 0, 0), a1 = make_float4(0, 0, 0, 0);
    float d10 = 0.f, d11 = 0.f, d20 = 0.f, d21 = 0.f;
#pragma unroll
    for (int j = 0; j < TT; j++) {
        float c0 = g_f1[j], c1 = g_f1[TT + j];
        int s = g_rowptr[j * (NN + 1) + row], e = g_rowptr[j * (NN + 1) + row + 1];
        int len = e - s;
        int qs = s + ((len * q) >> 2), qe = s + ((len * (q + 1)) >> 2);
        const int* dp = g_dst + j * EE;
        const float* vp = g_valv + j * EE;
#pragma unroll 4
        for (int k = qs; k < qe; k++) {
            int d = dp[k];
            float v = vp[k];
            float w0 = c0 * v, w1 = c1 * v;
            H8 y = *(const H8*)&g_Y2h[d * 256 + lane * 8];
            float2 y00 = __half22float2(y.a);
            float2 y01 = __half22float2(y.b);
            float2 y10 = __half22float2(y.c);
            float2 y11 = __half22float2(y.d);
            a0.x += w0 * y00.x; a0.y += w0 * y00.y; a0.z += w0 * y01.x; a0.w += w0 * y01.y;
            a1.x += w1 * y10.x; a1.y += w1 * y10.y; a1.z += w1 * y11.x; a1.w += w1 * y11.y;
            float4 st = g_s2t3[d];
            float2 uu = g_u2[d];
            d10 += w0 * st.x; d11 += w1 * st.y;
            d20 += w0 * uu.x; d21 += w1 * uu.y;
        }
    }
    sm[w][0][lane] = a0.x; sm[w][1][lane] = a0.y; sm[w][2][lane] = a0.z; sm[w][3][lane] = a0.w;
    sm[w][4][lane] = a1.x; sm[w][5][lane] = a1.y; sm[w][6][lane] = a1.z; sm[w][7][lane] = a1.w;
    if (lane == 0) { smd[w][0] = d10; smd[w][1] = d11; smd[w][2] = d20; smd[w][3] = d21; }
    __syncthreads();
    if (q == 0) {
        float vals[8];
#pragma unroll
        for (int i = 0; i < 8; i++)
            vals[i] = sm[w][i][lane] + sm[w + 1][i][lane] + sm[w + 2][i][lane] + sm[w + 3][i][lane];
        float D10 = smd[w][0] + smd[w + 1][0] + smd[w + 2][0] + smd[w + 3][0];
        float D11 = smd[w][1] + smd[w + 1][1] + smd[w + 2][1] + smd[w + 3][1];
        float D20 = smd[w][2] + smd[w + 1][2] + smd[w + 2][2] + smd[w + 3][2];
        float D21 = smd[w][3] + smd[w + 1][3] + smd[w + 2][3] + smd[w + 3][3];
        float i10 = (D10 == 0.f) ? 0.f : 1.f / D10;
        float dg0 = i10 * D20;
        float i20 = (dg0 == 0.f) ? 0.f : 1.f / dg0;
        float sc0 = i10 * i20;
        float i11 = (D11 == 0.f) ? 0.f : 1.f / D11;
        float dg1 = i11 * D21;
        float i21 = (dg1 == 0.f) ? 0.f : 1.f / dg1;
        float sc1 = i11 * i21;
        float4 bb = *(const float4*)&gcn_b[lane * 4];
        float o0[4], o1[4];
        o0[0] = fmaxf(sc0 * vals[0] + bb.x, 0.f);
        o0[1] = fmaxf(sc0 * vals[1] + bb.y, 0.f);
        o0[2] = fmaxf(sc0 * vals[2] + bb.z, 0.f);
        o0[3] = fmaxf(sc0 * vals[3] + bb.w, 0.f);
        o1[0] = fmaxf(sc1 * vals[4] + bb.x, 0.f);
        o1[1] = fmaxf(sc1 * vals[5] + bb.y, 0.f);
        o1[2] = fmaxf(sc1 * vals[6] + bb.z, 0.f);
        o1[3] = fmaxf(sc1 * vals[7] + bb.w, 0.f);
#pragma unroll
        for (int i = 0; i < 4; i++) {
            xts[tloc][0 * WOUT + lane * 4 + i] = o0[i];
            xts[tloc][1 * WOUT + lane * 4 + i] = o1[i];
        }
    }
    __syncthreads();
    // final linear: warps 0 and 4, lanes 0-15 each compute one class
    if (q == 0 && lane < NCLS) {
        float acc = lin_b[lane];
#pragma unroll 8
        for (int k = 0; k < CC * WOUT; k++)
            acc += xts[tloc][k] * lin_w[k * NCLS + lane];
        out[t * NCLS + lane] = acc;
    }
}

// ---------------- launch ----------------
extern "C" void kernel_launch(void* const* d_in, const int* in_sizes, int n_in,
                              void* d_out, int out_size) {
    const int*   edge_index = (const int*)d_in[0];
    const float* edge_value = (const float*)d_in[1];
    const float* X          = (const float*)d_in[2];
    const int*   target_x   = (const int*)d_in[3];
    const float* w_l0_c1    = (const float*)d_in[4];
    const float* w_l0_c2    = (const float*)d_in[5];
    const float* w_l1_c1    = (const float*)d_in[6];
    const float* gcn_w      = (const float*)d_in[7];
    const float* gcn_b      = (const float*)d_in[8];
    const float* lin_w      = (const float*)d_in[9];
    const float* lin_b      = (const float*)d_in[10];
    float* out = (float*)d_out;

    prep_k<<<209, 256>>>(X, gcn_w, w_l0_c1, w_l0_c2, w_l1_c1);
    count_k<<<(TT * EE + 255) / 256, 256>>>(edge_index, edge_value);
    scan_s2t3_k<<<TT + 16, 256>>>();
    scatter_k<<<(TT * EE + 255) / 256, 256>>>(edge_index, edge_value);
    stageAu_k<<<2560, 256>>>();
    stageB_k<<<2048, 256>>>();
    stageC_k<<<NT / 2, 256>>>(target_x, gcn_b, lin_w, lin_b, out);
}